// round 7
// baseline (speedup 1.0000x reference)
#include <cuda_runtime.h>
#include <cstdint>

#define IMG_W 4096
#define IMG_H 4096
#define PX    4   // pixels per thread

// Compute 4 output codes for pixels x0..x0+3 given the 3x6 neighborhood rows.
// n0 = row above, n1 = center row, n2 = row below (cols x0-1 .. x0+4).
__device__ __forceinline__ void kirsch_px4(const float n0[6], const float n1[6],
                                           const float n2[6], float code[PX]) {
    // Shared partials: top/bottom horizontal pairs, vertical column triples.
    float pt[PX + 1], pb[PX + 1], V[PX + 2];
#pragma unroll
    for (int i = 0; i < PX + 1; i++) {
        pt[i] = n0[i] + n0[i + 1];
        pb[i] = n2[i] + n2[i + 1];
    }
#pragma unroll
    for (int i = 0; i < PX + 2; i++) V[i] = n0[i] + n1[i] + n2[i];

#pragma unroll
    for (int j = 1; j <= PX; j++) {
        // neighborhood: a=n0[j-1] b=n0[j] c=n0[j+1]
        //               d=n1[j-1]        e=n1[j+1]
        //               f=n2[j-1] g=n2[j] h=n2[j+1]
        const float c = n0[j + 1];
        const float d = n1[j - 1];
        const float e = n1[j + 1];
        const float h = n2[j + 1];

        // Kirsch response R_k = 8*P_k - 3*T (T per-pixel const) => order by P_k.
        float P[8];
        P[0] = V[j + 1];        // c+e+h  (N)
        P[1] = pt[j] + e;       // b+c+e  (NW)
        P[2] = pt[j - 1] + c;   // a+b+c  (W)
        P[3] = pt[j - 1] + d;   // a+b+d  (SW)
        P[4] = V[j - 1];        // a+d+f  (S)
        P[5] = pb[j - 1] + d;   // d+f+g  (SE)
        P[6] = pb[j - 1] + h;   // f+g+h  (E)
        P[7] = pb[j] + e;       // e+g+h  (NE)

        // All P >= 0 => signed int compare of float bits == float compare.
        // tmp = bits & ~7 (low 3 bits cleared) => distinct tmp differ by >= 8,
        // while embedded index addends differ by <= 7, so order is exact.
        int tmp[8];
#pragma unroll
        for (int di = 0; di < 8; di++)
            tmp[di] = (int)(__float_as_uint(P[di]) & ~7u);   // 1 LOP3 each

        // Min side: min(tmp+di) -> exact ties pick smallest di (first index).
        int wmin = tmp[0];
        wmin = __viaddmin_s32(tmp[1], 1, wmin);
        wmin = __viaddmin_s32(tmp[2], 2, wmin);
        wmin = __viaddmin_s32(tmp[3], 3, wmin);
        wmin = __viaddmin_s32(tmp[4], 4, wmin);
        wmin = __viaddmin_s32(tmp[5], 5, wmin);
        wmin = __viaddmin_s32(tmp[6], 6, wmin);
        wmin = __viaddmin_s32(tmp[7], 7, wmin);

        // Max side: max(tmp-di) -> equal tmp give strictly decreasing values in
        // di, so exact ties pick smallest di (first index), matching argmax.
        // Index recovery: wmax = tmp_w - w  =>  (-wmax) & 7 == w.
        int wmax = tmp[0];
        wmax = __viaddmax_s32(tmp[1], -1, wmax);
        wmax = __viaddmax_s32(tmp[2], -2, wmax);
        wmax = __viaddmax_s32(tmp[3], -3, wmax);
        wmax = __viaddmax_s32(tmp[4], -4, wmax);
        wmax = __viaddmax_s32(tmp[5], -5, wmax);
        wmax = __viaddmax_s32(tmp[6], -6, wmax);
        wmax = __viaddmax_s32(tmp[7], -7, wmax);

        // code = 8*am + an; int->float via exponent-bias trick (FADD on the
        // under-used fma pipe instead of I2F on the alu pipe).
        const unsigned am = (0u - (unsigned)wmax) & 7u;
        const unsigned cb = 0x4B000000u | (am << 3) | ((unsigned)wmin & 7u);
        code[j - 1] = __uint_as_float(cb) - 8388608.0f;
    }
}

// Load 6 floats (cols x0-1 .. x0+4) from a valid row base pointer p = row+x0.
__device__ __forceinline__ void load6(float* n, const float* __restrict__ p,
                                      bool lft, bool rgt) {
    float4 v = __ldg(reinterpret_cast<const float4*>(p));
    n[1] = v.x; n[2] = v.y; n[3] = v.z; n[4] = v.w;
    n[0] = lft ? __ldg(p - 1) : 0.0f;
    n[5] = rgt ? __ldg(p + PX) : 0.0f;
}

// Interior rows: y in [1, IMG_H-2], no y-bounds code at all.
__global__ __launch_bounds__(256)
void kirsch_interior(const float* __restrict__ img, float* __restrict__ out) {
    const int x0 = (blockIdx.x * blockDim.x + threadIdx.x) * PX;
    const int y  = blockIdx.y + 1;
    const bool lft = (x0 > 0);
    const bool rgt = (x0 + PX < IMG_W);

    const float* p = img + (size_t)y * IMG_W + x0;
    float n0[6], n1[6], n2[6];
    load6(n0, p - IMG_W, lft, rgt);
    load6(n1, p,         lft, rgt);
    load6(n2, p + IMG_W, lft, rgt);

    float code[PX];
    kirsch_px4(n0, n1, n2, code);

    float4* o = reinterpret_cast<float4*>(out + (size_t)y * IMG_W + x0);
    *o = make_float4(code[0], code[1], code[2], code[3]);
}

// Edge rows: y = 0 and y = IMG_H-1, with zero-padded missing row.
__global__ __launch_bounds__(256)
void kirsch_edge(const float* __restrict__ img, float* __restrict__ out) {
    const int x0 = (blockIdx.x * blockDim.x + threadIdx.x) * PX;
    const int y  = blockIdx.y ? (IMG_H - 1) : 0;
    const bool lft = (x0 > 0);
    const bool rgt = (x0 + PX < IMG_W);

    const float* p = img + (size_t)y * IMG_W + x0;
    float n0[6], n1[6], n2[6];
    if (y > 0) load6(n0, p - IMG_W, lft, rgt);
    else {
#pragma unroll
        for (int i = 0; i < 6; i++) n0[i] = 0.0f;
    }
    load6(n1, p, lft, rgt);
    if (y < IMG_H - 1) load6(n2, p + IMG_W, lft, rgt);
    else {
#pragma unroll
        for (int i = 0; i < 6; i++) n2[i] = 0.0f;
    }

    float code[PX];
    kirsch_px4(n0, n1, n2, code);

    float4* o = reinterpret_cast<float4*>(out + (size_t)y * IMG_W + x0);
    *o = make_float4(code[0], code[1], code[2], code[3]);
}

extern "C" void kernel_launch(void* const* d_in, const int* in_sizes, int n_in,
                              void* d_out, int out_size) {
    const float* img = (const float*)d_in[0];
    for (int i = 0; i < n_in; i++) {
        if (in_sizes[i] == IMG_W * IMG_H) { img = (const float*)d_in[i]; break; }
    }
    float* out = (float*)d_out;

    dim3 block(256, 1, 1);
    dim3 gridI(IMG_W / (256 * PX), IMG_H - 2, 1);  // (4, 4094)
    dim3 gridE(IMG_W / (256 * PX), 2, 1);          // y = 0 and y = 4095
    kirsch_interior<<<gridI, block>>>(img, out);
    kirsch_edge<<<gridE, block>>>(img, out);
}

// round 8
// speedup vs baseline: 1.0352x; 1.0352x over previous
#include <cuda_runtime.h>
#include <cstdint>

#define IMG_W 4096
#define IMG_H 4096
#define PX    4   // pixels per thread

// Load 6 consecutive floats (cols x0-1 .. x0+4) of row yy, zero-padded.
__device__ __forceinline__ void load_row6(float* n, const float* __restrict__ img,
                                          int yy, int x0) {
    if ((unsigned)yy >= (unsigned)IMG_H) {
#pragma unroll
        for (int i = 0; i < 6; i++) n[i] = 0.0f;
        return;
    }
    const float* p = img + (size_t)yy * IMG_W + x0;
    float4 v = __ldg(reinterpret_cast<const float4*>(p));
    n[1] = v.x; n[2] = v.y; n[3] = v.z; n[4] = v.w;
    n[0] = (x0 > 0)          ? __ldg(p - 1) : 0.0f;
    n[5] = (x0 + PX < IMG_W) ? __ldg(p + PX) : 0.0f;
}

__global__ __launch_bounds__(256)
void kirsch_mask_kernel(const float* __restrict__ img, float* __restrict__ out) {
    const int x0 = (blockIdx.x * blockDim.x + threadIdx.x) * PX;
    const int y  = blockIdx.y;

    float n0[6], n1[6], n2[6];
    load_row6(n0, img, y - 1, x0);
    load_row6(n1, img, y,     x0);
    load_row6(n2, img, y + 1, x0);

    // Shared partials: top/bottom horizontal pairs, vertical column triples.
    float pt[PX + 1], pb[PX + 1], V[PX + 2];
#pragma unroll
    for (int i = 0; i < PX + 1; i++) {
        pt[i] = n0[i] + n0[i + 1];
        pb[i] = n2[i] + n2[i + 1];
    }
#pragma unroll
    for (int i = 0; i < PX + 2; i++) V[i] = n0[i] + n1[i] + n2[i];

    float code[PX];
#pragma unroll
    for (int j = 1; j <= PX; j++) {
        // neighborhood: a=n0[j-1] b=n0[j] c=n0[j+1]
        //               d=n1[j-1]        e=n1[j+1]
        //               f=n2[j-1] g=n2[j] h=n2[j+1]
        const float c = n0[j + 1];
        const float d = n1[j - 1];
        const float e = n1[j + 1];
        const float h = n2[j + 1];

        // Kirsch response R_k = 8*P_k - 3*T (T per-pixel const) => order by P_k.
        float P[8];
        P[0] = V[j + 1];        // c+e+h  (N)
        P[1] = pt[j] + e;       // b+c+e  (NW)
        P[2] = pt[j - 1] + c;   // a+b+c  (W)
        P[3] = pt[j - 1] + d;   // a+b+d  (SW)
        P[4] = V[j - 1];        // a+d+f  (S)
        P[5] = pb[j - 1] + d;   // d+f+g  (SE)
        P[6] = pb[j - 1] + h;   // f+g+h  (E)
        P[7] = pb[j] + e;       // e+g+h  (NE)

        // All P >= 0 => signed int compare of float bits == float compare.
        // tmp = bits & ~7: distinct tmp differ by >= 8 > |index addends|,
        // so ordering is exact; masked-equal ties resolve to smallest index
        // on both sides (min: +di ascending; max: -di descending).
        int tmp[8];
#pragma unroll
        for (int di = 0; di < 8; di++)
            tmp[di] = (int)(__float_as_uint(P[di]) & ~7u);   // 1 LOP3 each

        // Index-attach as separate integer adds (pipe-flexible: IADD3 or IMAD)
        // feeding 3-input VIMNMX3 trees (4 ALU ops per side instead of 7).
        int wmin = __vimin3_s32(tmp[0], tmp[1] + 1, tmp[2] + 2);
        int t2   = __vimin3_s32(tmp[3] + 3, tmp[4] + 4, tmp[5] + 5);
        int t3   = min(tmp[6] + 6, tmp[7] + 7);
        wmin = __vimin3_s32(wmin, t2, t3);

        int wmax = __vimax3_s32(tmp[0], tmp[1] - 1, tmp[2] - 2);
        int u2   = __vimax3_s32(tmp[3] - 3, tmp[4] - 4, tmp[5] - 5);
        int u3   = max(tmp[6] - 6, tmp[7] - 7);
        wmax = __vimax3_s32(wmax, u2, u3);

        // wmax = tmp_w - w (tmp_w multiple of 8) => (-wmax) & 7 == w.
        // code = 8*am + an; int->float via exponent-bias trick (FADD on the
        // fma pipe instead of I2F on the alu pipe).
        const unsigned am = (0u - (unsigned)wmax) & 7u;
        const unsigned cb = 0x4B000000u | (am << 3) | ((unsigned)wmin & 7u);
        code[j - 1] = __uint_as_float(cb) - 8388608.0f;
    }

    float4* o = reinterpret_cast<float4*>(out + (size_t)y * IMG_W + x0);
    *o = make_float4(code[0], code[1], code[2], code[3]);
}

extern "C" void kernel_launch(void* const* d_in, const int* in_sizes, int n_in,
                              void* d_out, int out_size) {
    const float* img = (const float*)d_in[0];
    for (int i = 0; i < n_in; i++) {
        if (in_sizes[i] == IMG_W * IMG_H) { img = (const float*)d_in[i]; break; }
    }
    float* out = (float*)d_out;

    dim3 block(256, 1, 1);
    dim3 grid(IMG_W / (256 * PX), IMG_H, 1);  // (4, 4096)
    kirsch_mask_kernel<<<grid, block>>>(img, out);
}

// round 9
// speedup vs baseline: 1.1594x; 1.1200x over previous
#include <cuda_runtime.h>
#include <cstdint>

#define IMG_W 4096
#define IMG_H 4096
#define PX    4   // pixels per thread in x; 2 rows per thread => 8 px/thread

// Load 6 consecutive floats (cols x0-1 .. x0+4) of row yy, zero-padded in y.
__device__ __forceinline__ void load_row6(float* n, const float* __restrict__ img,
                                          int yy, int x0, bool lft, bool rgt) {
    if ((unsigned)yy >= (unsigned)IMG_H) {
#pragma unroll
        for (int i = 0; i < 6; i++) n[i] = 0.0f;
        return;
    }
    const float* p = img + (size_t)yy * IMG_W + x0;
    float4 v = __ldg(reinterpret_cast<const float4*>(p));
    n[1] = v.x; n[2] = v.y; n[3] = v.z; n[4] = v.w;
    n[0] = lft ? __ldg(p - 1) : 0.0f;
    n[5] = rgt ? __ldg(p + PX) : 0.0f;
}

// Codes for 4 pixels given rows above/center/below (cols x0-1..x0+4).
// Exact same decision procedure as the 39.4us kernel (R6): bit-compare of
// P-sums with index embedded via fused VIADDMNMX; ties -> first index.
__device__ __forceinline__ void kirsch_px4(const float n0[6], const float n1[6],
                                           const float n2[6], float code[PX]) {
    float pt[PX + 1], pb[PX + 1], V[PX + 2];
#pragma unroll
    for (int i = 0; i < PX + 1; i++) {
        pt[i] = n0[i] + n0[i + 1];
        pb[i] = n2[i] + n2[i + 1];
    }
#pragma unroll
    for (int i = 0; i < PX + 2; i++) V[i] = n0[i] + n1[i] + n2[i];

#pragma unroll
    for (int j = 1; j <= PX; j++) {
        const float c = n0[j + 1];
        const float d = n1[j - 1];
        const float e = n1[j + 1];
        const float h = n2[j + 1];

        // Kirsch response R_k = 8*P_k - 3*T (T per-pixel const) => order by P_k.
        float P[8];
        P[0] = V[j + 1];        // c+e+h  (N)
        P[1] = pt[j] + e;       // b+c+e  (NW)
        P[2] = pt[j - 1] + c;   // a+b+c  (W)
        P[3] = pt[j - 1] + d;   // a+b+d  (SW)
        P[4] = V[j - 1];        // a+d+f  (S)
        P[5] = pb[j - 1] + d;   // d+f+g  (SE)
        P[6] = pb[j - 1] + h;   // f+g+h  (E)
        P[7] = pb[j] + e;       // e+g+h  (NE)

        // All P >= 0 => signed int compare of float bits == float compare.
        // tmp = bits & ~7: distinct tmp differ by >= 8 > |index addends|.
        int tmp[8];
#pragma unroll
        for (int di = 0; di < 8; di++)
            tmp[di] = (int)(__float_as_uint(P[di]) & ~7u);

        // min(tmp+di): ties pick smallest di (first index).
        int wmin = tmp[0];
        wmin = __viaddmin_s32(tmp[1], 1, wmin);
        wmin = __viaddmin_s32(tmp[2], 2, wmin);
        wmin = __viaddmin_s32(tmp[3], 3, wmin);
        wmin = __viaddmin_s32(tmp[4], 4, wmin);
        wmin = __viaddmin_s32(tmp[5], 5, wmin);
        wmin = __viaddmin_s32(tmp[6], 6, wmin);
        wmin = __viaddmin_s32(tmp[7], 7, wmin);

        // max(tmp-di): ties pick smallest di; recover via (-wmax)&7.
        int wmax = tmp[0];
        wmax = __viaddmax_s32(tmp[1], -1, wmax);
        wmax = __viaddmax_s32(tmp[2], -2, wmax);
        wmax = __viaddmax_s32(tmp[3], -3, wmax);
        wmax = __viaddmax_s32(tmp[4], -4, wmax);
        wmax = __viaddmax_s32(tmp[5], -5, wmax);
        wmax = __viaddmax_s32(tmp[6], -6, wmax);
        wmax = __viaddmax_s32(tmp[7], -7, wmax);

        // code = 8*am + an; int->float via exponent-bias trick (FADD on fma pipe).
        const unsigned am = (0u - (unsigned)wmax) & 7u;
        const unsigned cb = 0x4B000000u | (am << 3) | ((unsigned)wmin & 7u);
        code[j - 1] = __uint_as_float(cb) - 8388608.0f;
    }
}

// 2 output rows per thread: rows y, y+1 need input rows y-1..y+2 (4 loads
// instead of 6) => LDG/px drops 2.25 -> 1.5. Compute row y and store it
// BEFORE row y+1's partials to keep register live set small.
__global__ __launch_bounds__(256)
void kirsch_mask_kernel(const float* __restrict__ img, float* __restrict__ out) {
    const int x0 = (blockIdx.x * blockDim.x + threadIdx.x) * PX;
    const int y  = blockIdx.y * 2;
    const bool lft = (x0 > 0);
    const bool rgt = (x0 + PX < IMG_W);

    float r0[6], r1[6], r2[6], r3[6];
    load_row6(r0, img, y - 1, x0, lft, rgt);
    load_row6(r1, img, y,     x0, lft, rgt);  // always in-range
    load_row6(r2, img, y + 1, x0, lft, rgt);  // always in-range (y+1 <= 4095)
    load_row6(r3, img, y + 2, x0, lft, rgt);

    float code[PX];
    kirsch_px4(r0, r1, r2, code);
    float4* oA = reinterpret_cast<float4*>(out + (size_t)y * IMG_W + x0);
    *oA = make_float4(code[0], code[1], code[2], code[3]);

    kirsch_px4(r1, r2, r3, code);
    float4* oB = reinterpret_cast<float4*>(out + (size_t)(y + 1) * IMG_W + x0);
    *oB = make_float4(code[0], code[1], code[2], code[3]);
}

extern "C" void kernel_launch(void* const* d_in, const int* in_sizes, int n_in,
                              void* d_out, int out_size) {
    const float* img = (const float*)d_in[0];
    for (int i = 0; i < n_in; i++) {
        if (in_sizes[i] == IMG_W * IMG_H) { img = (const float*)d_in[i]; break; }
    }
    float* out = (float*)d_out;

    dim3 block(256, 1, 1);
    dim3 grid(IMG_W / (256 * PX), IMG_H / 2, 1);  // (4, 2048)
    kirsch_mask_kernel<<<grid, block>>>(img, out);
}